// round 2
// baseline (speedup 1.0000x reference)
#include <cuda_runtime.h>
#include <cuda_bf16.h>

// Problem dims
#define HH 512
#define EE 256
#define VV 50000
#define BB 128
#define SS 200
#define H2 (2*HH)      // 1024
#define H3 (3*HH)      // 1536
#define KG (H2+EE)     // 1280  (GRU input width)
#define KO (H3+EE)     // 1792  (output proj width)

// ---------------- device scratch (no allocation allowed) ----------------
__device__ float g_u2[H2];                 // attn_w[:,H:3H]^T @ v
__device__ float g_scores[BB*SS];          // scores -> attn weights (in place)
__device__ float g_togru[BB*KG];           // relu(concat(emb_x, context))
__device__ float g_toout[BB*KO];           // concat(h_new, context, emb_x)
__device__ float g_gi[BB*H3];
__device__ float g_gh[BB*H3];

// ---------------- K1: u2[k] = sum_h attn_w[h, H+k] * v[h] ----------------
__global__ void k_u2(const float* __restrict__ attn_w, const float* __restrict__ v) {
    int k = threadIdx.x;  // 1024 threads
    float acc = 0.f;
    #pragma unroll 4
    for (int h = 0; h < HH; h++)
        acc += attn_w[h * H3 + HH + k] * v[h];
    g_u2[k] = acc;
}

// ---------------- K2: emb gather -> togru[:, 0:E] (relu) and toout[:, 3H:3H+E]
__global__ void k_emb(const int* __restrict__ x, const float* __restrict__ emb) {
    int b = blockIdx.x;
    int e = threadIdx.x;  // 256
    float val = emb[(long)x[b] * EE + e];
    g_togru[b * KG + e] = fmaxf(val, 0.f);
    g_toout[b * KO + H3 + e] = val;
}

// ---------------- K3: scores[b,s] = enc_out[b,s,:] . u2  (one warp per (b,s))
__global__ void k_scores(const float* __restrict__ enc) {
    int w = blockIdx.x * 8 + (threadIdx.x >> 5);
    int lane = threadIdx.x & 31;
    if (w >= BB * SS) return;
    int b = w / SS, s = w % SS;
    const float* ep = enc + (long)b * SS * H2 + (long)s * H2;
    float acc = 0.f;
    #pragma unroll
    for (int i = 0; i < 8; i++) {
        float4 e4 = *reinterpret_cast<const float4*>(ep + i * 128 + lane * 4);
        float4 u4 = *reinterpret_cast<const float4*>(g_u2 + i * 128 + lane * 4);
        acc += e4.x * u4.x + e4.y * u4.y + e4.z * u4.z + e4.w * u4.w;
    }
    #pragma unroll
    for (int o = 16; o > 0; o >>= 1) acc += __shfl_xor_sync(0xffffffffu, acc, o);
    if (lane == 0) g_scores[b * SS + s] = acc;
}

// ---------------- K4: softmax over S per row ----------------
__global__ void k_softmax() {
    int b = blockIdx.x, t = threadIdx.x;  // 256 threads
    __shared__ float red[256];
    float val = (t < SS) ? g_scores[b * SS + t] : -1e30f;
    red[t] = val; __syncthreads();
    for (int s = 128; s > 0; s >>= 1) { if (t < s) red[t] = fmaxf(red[t], red[t + s]); __syncthreads(); }
    float m = red[0]; __syncthreads();
    float e = (t < SS) ? expf(val - m) : 0.f;
    red[t] = e; __syncthreads();
    for (int s = 128; s > 0; s >>= 1) { if (t < s) red[t] += red[t + s]; __syncthreads(); }
    float inv = 1.f / red[0];
    if (t < SS) g_scores[b * SS + t] = e * inv;
}

// ---------------- K5: context[b,d] = sum_s attn[b,s]*enc[b,s,d]
// also writes togru[:, E:E+2H] (relu) and toout[:, H:3H]
__global__ void k_context(const float* __restrict__ enc) {
    int b = blockIdx.x;
    int d = blockIdx.y * 256 + threadIdx.x;
    __shared__ float sa[SS];
    if (threadIdx.x < SS) sa[threadIdx.x] = g_scores[b * SS + threadIdx.x];
    __syncthreads();
    const float* ep = enc + (long)b * SS * H2 + d;
    float acc = 0.f;
    #pragma unroll 4
    for (int s = 0; s < SS; s++)
        acc += sa[s] * ep[(long)s * H2];
    g_togru[b * KG + EE + d] = fmaxf(acc, 0.f);
    g_toout[b * KO + HH + d] = acc;
}

// ---------------- SGEMM: C[M,N] = A[M,K] @ W[N,K]^T + bias  (M == 128) ----
// 128x128 block tile, 8x8 thread tile, BK=8, 256 threads.
__global__ void __launch_bounds__(256)
k_sgemm(const float* __restrict__ A, const float* __restrict__ W,
        const float* __restrict__ bias, float* __restrict__ C, int N, int K) {
    __shared__ float As[8][132];
    __shared__ float Ws[8][132];
    int tid = threadIdx.x;
    int n0 = blockIdx.x * 128;
    int tm = (tid / 16) * 8;
    int tn = (tid % 16) * 8;
    int a_m = tid >> 1;
    int k4 = (tid & 1) * 4;
    float acc[8][8];
    #pragma unroll
    for (int i = 0; i < 8; i++)
        #pragma unroll
        for (int j = 0; j < 8; j++) acc[i][j] = 0.f;

    for (int k0 = 0; k0 < K; k0 += 8) {
        float4 av = *reinterpret_cast<const float4*>(A + (long)a_m * K + k0 + k4);
        As[k4 + 0][a_m] = av.x; As[k4 + 1][a_m] = av.y;
        As[k4 + 2][a_m] = av.z; As[k4 + 3][a_m] = av.w;
        int ng = n0 + a_m;
        float4 wv = make_float4(0.f, 0.f, 0.f, 0.f);
        if (ng < N) wv = *reinterpret_cast<const float4*>(W + (long)ng * K + k0 + k4);
        Ws[k4 + 0][a_m] = wv.x; Ws[k4 + 1][a_m] = wv.y;
        Ws[k4 + 2][a_m] = wv.z; Ws[k4 + 3][a_m] = wv.w;
        __syncthreads();
        #pragma unroll
        for (int k = 0; k < 8; k++) {
            float4 a0 = *reinterpret_cast<const float4*>(&As[k][tm]);
            float4 a1 = *reinterpret_cast<const float4*>(&As[k][tm + 4]);
            float4 w0 = *reinterpret_cast<const float4*>(&Ws[k][tn]);
            float4 w1 = *reinterpret_cast<const float4*>(&Ws[k][tn + 4]);
            float av8[8] = {a0.x, a0.y, a0.z, a0.w, a1.x, a1.y, a1.z, a1.w};
            float wv8[8] = {w0.x, w0.y, w0.z, w0.w, w1.x, w1.y, w1.z, w1.w};
            #pragma unroll
            for (int i = 0; i < 8; i++)
                #pragma unroll
                for (int j = 0; j < 8; j++)
                    acc[i][j] += av8[i] * wv8[j];
        }
        __syncthreads();
    }
    #pragma unroll
    for (int i = 0; i < 8; i++) {
        int m = tm + i;
        #pragma unroll
        for (int j = 0; j < 8; j++) {
            int n = n0 + tn + j;
            if (n < N) C[(long)m * N + n] = acc[i][j] + bias[n];
        }
    }
}

// ---------------- K8: GRU gate fuse -> h_new ----------------
__global__ void k_gates(const float* __restrict__ h0, float* __restrict__ h_out) {
    int idx = blockIdx.x * 256 + threadIdx.x;  // B*H total
    int b = idx / HH, h = idx % HH;
    float i_r = g_gi[b * H3 + h],        h_r = g_gh[b * H3 + h];
    float i_z = g_gi[b * H3 + HH + h],   h_z = g_gh[b * H3 + HH + h];
    float i_n = g_gi[b * H3 + 2*HH + h], h_n = g_gh[b * H3 + 2*HH + h];
    float r = 1.f / (1.f + expf(-(i_r + h_r)));
    float z = 1.f / (1.f + expf(-(i_z + h_z)));
    float n = tanhf(i_n + r * h_n);
    float hn = (1.f - z) * n + z * h0[idx];
    h_out[idx] = hn;
    g_toout[b * KO + h] = hn;
}

// ---------------- launch ----------------
extern "C" void kernel_launch(void* const* d_in, const int* in_sizes, int n_in,
                              void* d_out, int out_size) {
    const int*   x      = (const int*)  d_in[0];
    const float* hidden = (const float*)d_in[1];
    const float* enc    = (const float*)d_in[2];
    const float* emb    = (const float*)d_in[3];
    const float* attn_w = (const float*)d_in[4];
    // d_in[5] = attn_b (cancels in softmax), d_in[6] = v
    const float* v      = (const float*)d_in[6];
    const float* w_ih   = (const float*)d_in[7];
    const float* w_hh   = (const float*)d_in[8];
    const float* b_ih   = (const float*)d_in[9];
    const float* b_hh   = (const float*)d_in[10];
    const float* out_w  = (const float*)d_in[11];
    const float* out_b  = (const float*)d_in[12];

    float* out_logits = (float*)d_out;                    // [B, V]
    float* out_hidden = out_logits + (long)BB * VV;       // [1, B, H]

    // Resolve device-symbol addresses properly (host code must NOT take the
    // address of a __device__ variable directly — that was the round-1 bug).
    float *p_togru = nullptr, *p_toout = nullptr, *p_gi = nullptr, *p_gh = nullptr;
    cudaGetSymbolAddress((void**)&p_togru, g_togru);
    cudaGetSymbolAddress((void**)&p_toout, g_toout);
    cudaGetSymbolAddress((void**)&p_gi,    g_gi);
    cudaGetSymbolAddress((void**)&p_gh,    g_gh);

    k_u2<<<1, 1024>>>(attn_w, v);
    k_emb<<<BB, 256>>>(x, emb);
    k_scores<<<(BB * SS + 7) / 8, 256>>>(enc);
    k_softmax<<<BB, 256>>>();
    k_context<<<dim3(BB, H2 / 256), 256>>>(enc);
    k_sgemm<<<H3 / 128, 256>>>(p_togru, w_ih, b_ih, p_gi, H3, KG);
    k_sgemm<<<H3 / 128, 256>>>(hidden, w_hh, b_hh, p_gh, H3, HH);
    k_gates<<<BB * HH / 256, 256>>>(hidden, out_hidden);
    k_sgemm<<<(VV + 127) / 128, 256>>>(p_toout, out_w, out_b, out_logits, VV, KO);
}

// round 4
// speedup vs baseline: 1.6579x; 1.6579x over previous
#include <cuda_runtime.h>
#include <cuda_bf16.h>
#include <mma.h>
#include <cstdint>

using namespace nvcuda;

// Problem dims
#define HH 512
#define EE 256
#define VV 50000
#define BB 128
#define SS 200
#define H2 (2*HH)      // 1024
#define H3 (3*HH)      // 1536
#define KG (H2+EE)     // 1280
#define KO (H3+EE)     // 1792

// ---------------- device scratch ----------------
__device__ float g_u2[H2];
__device__ float g_scores[BB*SS];
__device__ float g_togru[BB*KG];
__device__ float g_toout[BB*KO];
__device__ float g_gi[BB*H3];
__device__ float g_gh[BB*H3];
__device__ __nv_bfloat16 g_Ahi[BB*KO];
__device__ __nv_bfloat16 g_Alo[BB*KO];

// ===================================================================
// K1: u2[k] = sum_h attn_w[h, H+k] * v[h]
__global__ void k_u2(const float* __restrict__ attn_w, const float* __restrict__ v) {
    int k = threadIdx.x;  // 1024
    float acc = 0.f;
    #pragma unroll 4
    for (int h = 0; h < HH; h++)
        acc += attn_w[h * H3 + HH + k] * v[h];
    g_u2[k] = acc;
}

// K2: emb gather
__global__ void k_emb(const int* __restrict__ x, const float* __restrict__ emb) {
    int b = blockIdx.x;
    int e = threadIdx.x;
    float val = emb[(long)x[b] * EE + e];
    g_togru[b * KG + e] = fmaxf(val, 0.f);
    g_toout[b * KO + H3 + e] = val;
}

// K3: scores[b,s] = enc[b,s,:] . u2
__global__ void k_scores(const float* __restrict__ enc) {
    int w = blockIdx.x * 8 + (threadIdx.x >> 5);
    int lane = threadIdx.x & 31;
    if (w >= BB * SS) return;
    int b = w / SS, s = w % SS;
    const float* ep = enc + (long)b * SS * H2 + (long)s * H2;
    float acc = 0.f;
    #pragma unroll
    for (int i = 0; i < 8; i++) {
        float4 e4 = *reinterpret_cast<const float4*>(ep + i * 128 + lane * 4);
        float4 u4 = *reinterpret_cast<const float4*>(g_u2 + i * 128 + lane * 4);
        acc += e4.x * u4.x + e4.y * u4.y + e4.z * u4.z + e4.w * u4.w;
    }
    #pragma unroll
    for (int o = 16; o > 0; o >>= 1) acc += __shfl_xor_sync(0xffffffffu, acc, o);
    if (lane == 0) g_scores[b * SS + s] = acc;
}

// K4: softmax over S
__global__ void k_softmax() {
    int b = blockIdx.x, t = threadIdx.x;
    __shared__ float red[256];
    float val = (t < SS) ? g_scores[b * SS + t] : -1e30f;
    red[t] = val; __syncthreads();
    for (int s = 128; s > 0; s >>= 1) { if (t < s) red[t] = fmaxf(red[t], red[t + s]); __syncthreads(); }
    float m = red[0]; __syncthreads();
    float e = (t < SS) ? expf(val - m) : 0.f;
    red[t] = e; __syncthreads();
    for (int s = 128; s > 0; s >>= 1) { if (t < s) red[t] += red[t + s]; __syncthreads(); }
    float inv = 1.f / red[0];
    if (t < SS) g_scores[b * SS + t] = e * inv;
}

// K5: context
__global__ void k_context(const float* __restrict__ enc) {
    int b = blockIdx.x;
    int d = blockIdx.y * 256 + threadIdx.x;
    __shared__ float sa[SS];
    if (threadIdx.x < SS) sa[threadIdx.x] = g_scores[b * SS + threadIdx.x];
    __syncthreads();
    const float* ep = enc + (long)b * SS * H2 + d;
    float acc = 0.f;
    #pragma unroll 4
    for (int s = 0; s < SS; s++)
        acc += sa[s] * ep[(long)s * H2];
    g_togru[b * KG + EE + d] = fmaxf(acc, 0.f);
    g_toout[b * KO + HH + d] = acc;
}

// fp32 SGEMM for small GRU GEMMs
__global__ void __launch_bounds__(256)
k_sgemm(const float* __restrict__ A, const float* __restrict__ W,
        const float* __restrict__ bias, float* __restrict__ C, int N, int K) {
    __shared__ float As[8][132];
    __shared__ float Ws[8][132];
    int tid = threadIdx.x;
    int n0 = blockIdx.x * 128;
    int tm = (tid / 16) * 8;
    int tn = (tid % 16) * 8;
    int a_m = tid >> 1;
    int k4 = (tid & 1) * 4;
    float acc[8][8];
    #pragma unroll
    for (int i = 0; i < 8; i++)
        #pragma unroll
        for (int j = 0; j < 8; j++) acc[i][j] = 0.f;

    for (int k0 = 0; k0 < K; k0 += 8) {
        float4 av = *reinterpret_cast<const float4*>(A + (long)a_m * K + k0 + k4);
        As[k4 + 0][a_m] = av.x; As[k4 + 1][a_m] = av.y;
        As[k4 + 2][a_m] = av.z; As[k4 + 3][a_m] = av.w;
        int ng = n0 + a_m;
        float4 wv = make_float4(0.f, 0.f, 0.f, 0.f);
        if (ng < N) wv = *reinterpret_cast<const float4*>(W + (long)ng * K + k0 + k4);
        Ws[k4 + 0][a_m] = wv.x; Ws[k4 + 1][a_m] = wv.y;
        Ws[k4 + 2][a_m] = wv.z; Ws[k4 + 3][a_m] = wv.w;
        __syncthreads();
        #pragma unroll
        for (int k = 0; k < 8; k++) {
            float4 a0 = *reinterpret_cast<const float4*>(&As[k][tm]);
            float4 a1 = *reinterpret_cast<const float4*>(&As[k][tm + 4]);
            float4 w0 = *reinterpret_cast<const float4*>(&Ws[k][tn]);
            float4 w1 = *reinterpret_cast<const float4*>(&Ws[k][tn + 4]);
            float av8[8] = {a0.x, a0.y, a0.z, a0.w, a1.x, a1.y, a1.z, a1.w};
            float wv8[8] = {w0.x, w0.y, w0.z, w0.w, w1.x, w1.y, w1.z, w1.w};
            #pragma unroll
            for (int i = 0; i < 8; i++)
                #pragma unroll
                for (int j = 0; j < 8; j++)
                    acc[i][j] += av8[i] * wv8[j];
        }
        __syncthreads();
    }
    #pragma unroll
    for (int i = 0; i < 8; i++) {
        int m = tm + i;
        #pragma unroll
        for (int j = 0; j < 8; j++) {
            int n = n0 + tn + j;
            if (n < N) C[(long)m * N + n] = acc[i][j] + bias[n];
        }
    }
}

// K8: GRU gate fuse
__global__ void k_gates(const float* __restrict__ h0, float* __restrict__ h_out) {
    int idx = blockIdx.x * 256 + threadIdx.x;
    int b = idx / HH, h = idx % HH;
    float i_r = g_gi[b * H3 + h],        h_r = g_gh[b * H3 + h];
    float i_z = g_gi[b * H3 + HH + h],   h_z = g_gh[b * H3 + HH + h];
    float i_n = g_gi[b * H3 + 2*HH + h], h_n = g_gh[b * H3 + 2*HH + h];
    float r = 1.f / (1.f + expf(-(i_r + h_r)));
    float z = 1.f / (1.f + expf(-(i_z + h_z)));
    float n = tanhf(i_n + r * h_n);
    float hn = (1.f - z) * n + z * h0[idx];
    h_out[idx] = hn;
    g_toout[b * KO + h] = hn;
}

// K8b: split A (toout) into bf16 hi/lo once
__global__ void k_convA() {
    int idx = (blockIdx.x * 256 + threadIdx.x) * 4;
    float4 f = *reinterpret_cast<const float4*>(g_toout + idx);
    __nv_bfloat162 h0 = __floats2bfloat162_rn(f.x, f.y);
    __nv_bfloat162 h1 = __floats2bfloat162_rn(f.z, f.w);
    float lx = f.x - __bfloat162float(__low2bfloat16(h0));
    float ly = f.y - __bfloat162float(__high2bfloat16(h0));
    float lz = f.z - __bfloat162float(__low2bfloat16(h1));
    float lw = f.w - __bfloat162float(__high2bfloat16(h1));
    __nv_bfloat162 l0 = __floats2bfloat162_rn(lx, ly);
    __nv_bfloat162 l1 = __floats2bfloat162_rn(lz, lw);
    *reinterpret_cast<__nv_bfloat162*>(g_Ahi + idx)     = h0;
    *reinterpret_cast<__nv_bfloat162*>(g_Ahi + idx + 2) = h1;
    *reinterpret_cast<__nv_bfloat162*>(g_Alo + idx)     = l0;
    *reinterpret_cast<__nv_bfloat162*>(g_Alo + idx + 2) = l1;
}

// ===================================================================
// K9: logits GEMM via wmma bf16, hi/lo split (3 products).
// C[128,50000] = A[128,1792] @ W[50000,1792]^T + bias
// CTA: 128(M) x 64(N) tile, BK=64, 8 warps of 32x32, 2 CTAs/SM.
// ===================================================================
#define NTL 64
#define BKL 64
#define LDT 72          // smem leading dim (halves); 144B row stride kills LDSM conflicts
#define SMEM_LOGITS ((128*LDT*2 + NTL*LDT*2) * 2)   // Ah,Al,Wh,Wl = 55296 B

__global__ void __launch_bounds__(256, 2)
k_logits(const __nv_bfloat16* __restrict__ Ahi, const __nv_bfloat16* __restrict__ Alo,
         const float* __restrict__ W, const float* __restrict__ bias,
         float* __restrict__ C) {
    extern __shared__ char smem[];
    __nv_bfloat16* sAh = reinterpret_cast<__nv_bfloat16*>(smem);
    __nv_bfloat16* sAl = sAh + 128 * LDT;
    __nv_bfloat16* sWh = sAl + 128 * LDT;
    __nv_bfloat16* sWl = sWh + NTL * LDT;

    int tid = threadIdx.x;
    int wid = tid >> 5, lid = tid & 31;
    int n0 = blockIdx.x * NTL;
    int wm = (wid >> 1) * 32;
    int wn = (wid & 1) * 32;

    wmma::fragment<wmma::accumulator, 16, 16, 16, float> acc[2][2];
    #pragma unroll
    for (int i = 0; i < 2; i++)
        #pragma unroll
        for (int j = 0; j < 2; j++) wmma::fill_fragment(acc[i][j], 0.f);

    for (int kc = 0; kc < KO / BKL; kc++) {
        int k0 = kc * BKL;
        // --- A tiles: copy precomputed bf16 hi/lo (1024 uint4 per tile) ---
        #pragma unroll
        for (int j = 0; j < 4; j++) {
            int u = tid + j * 256;
            int r = u >> 3, q = u & 7;
            *reinterpret_cast<uint4*>(sAh + r * LDT + q * 8) =
                *reinterpret_cast<const uint4*>(Ahi + (long)r * KO + k0 + q * 8);
            *reinterpret_cast<uint4*>(sAl + r * LDT + q * 8) =
                *reinterpret_cast<const uint4*>(Alo + (long)r * KO + k0 + q * 8);
        }
        // --- W tile: LDG fp32, convert to bf16 hi/lo, STS (1024 float4) ---
        #pragma unroll
        for (int j = 0; j < 4; j++) {
            int u = tid + j * 256;
            int r = u >> 4, q = u & 15;
            int wr = n0 + r;
            float4 f = make_float4(0.f, 0.f, 0.f, 0.f);
            if (wr < VV)
                f = *reinterpret_cast<const float4*>(W + (long)wr * KO + k0 + q * 4);
            __nv_bfloat162 h0 = __floats2bfloat162_rn(f.x, f.y);
            __nv_bfloat162 h1 = __floats2bfloat162_rn(f.z, f.w);
            float lx = f.x - __bfloat162float(__low2bfloat16(h0));
            float ly = f.y - __bfloat162float(__high2bfloat16(h0));
            float lz = f.z - __bfloat162float(__low2bfloat16(h1));
            float lw = f.w - __bfloat162float(__high2bfloat16(h1));
            __nv_bfloat162 l0 = __floats2bfloat162_rn(lx, ly);
            __nv_bfloat162 l1 = __floats2bfloat162_rn(lz, lw);
            uint2 hv, lv;
            hv.x = *reinterpret_cast<uint32_t*>(&h0); hv.y = *reinterpret_cast<uint32_t*>(&h1);
            lv.x = *reinterpret_cast<uint32_t*>(&l0); lv.y = *reinterpret_cast<uint32_t*>(&l1);
            *reinterpret_cast<uint2*>(sWh + r * LDT + q * 4) = hv;
            *reinterpret_cast<uint2*>(sWl + r * LDT + q * 4) = lv;
        }
        __syncthreads();

        #pragma unroll
        for (int kk = 0; kk < BKL / 16; kk++) {
            int ks = kk * 16;
            wmma::fragment<wmma::matrix_a, 16, 16, 16, __nv_bfloat16, wmma::row_major> ah[2], al[2];
            wmma::fragment<wmma::matrix_b, 16, 16, 16, __nv_bfloat16, wmma::col_major> bh[2], bl[2];
            #pragma unroll
            for (int i = 0; i < 2; i++) {
                wmma::load_matrix_sync(ah[i], sAh + (wm + 16 * i) * LDT + ks, LDT);
                wmma::load_matrix_sync(al[i], sAl + (wm + 16 * i) * LDT + ks, LDT);
            }
            #pragma unroll
            for (int j = 0; j < 2; j++) {
                wmma::load_matrix_sync(bh[j], sWh + (wn + 16 * j) * LDT + ks, LDT);
                wmma::load_matrix_sync(bl[j], sWl + (wn + 16 * j) * LDT + ks, LDT);
            }
            #pragma unroll
            for (int i = 0; i < 2; i++)
                #pragma unroll
                for (int j = 0; j < 2; j++) {
                    wmma::mma_sync(acc[i][j], ah[i], bh[j], acc[i][j]);
                    wmma::mma_sync(acc[i][j], ah[i], bl[j], acc[i][j]);
                    wmma::mma_sync(acc[i][j], al[i], bh[j], acc[i][j]);
                }
        }
        __syncthreads();
    }

    // --- epilogue: stage via smem, add bias, coalesced STG ---
    float* stage = reinterpret_cast<float*>(smem) + wid * (32 * 36);
    #pragma unroll
    for (int i = 0; i < 2; i++)
        #pragma unroll
        for (int j = 0; j < 2; j++)
            wmma::store_matrix_sync(stage + i * 16 * 36 + j * 16, acc[i][j], 36, wmma::mem_row_major);
    __syncwarp();
    int n = n0 + wn + lid;
    if (n < VV) {
        float bs = bias[n];
        #pragma unroll 4
        for (int r = 0; r < 32; r++)
            C[(long)(wm + r) * VV + n] = stage[r * 36 + lid] + bs;
    }
}

// ---------------- launch ----------------
extern "C" void kernel_launch(void* const* d_in, const int* in_sizes, int n_in,
                              void* d_out, int out_size) {
    const int*   x      = (const int*)  d_in[0];
    const float* hidden = (const float*)d_in[1];
    const float* enc    = (const float*)d_in[2];
    const float* emb    = (const float*)d_in[3];
    const float* attn_w = (const float*)d_in[4];
    const float* v      = (const float*)d_in[6];
    const float* w_ih   = (const float*)d_in[7];
    const float* w_hh   = (const float*)d_in[8];
    const float* b_ih   = (const float*)d_in[9];
    const float* b_hh   = (const float*)d_in[10];
    const float* out_w  = (const float*)d_in[11];
    const float* out_b  = (const float*)d_in[12];

    float* out_logits = (float*)d_out;
    float* out_hidden = out_logits + (long)BB * VV;

    float *p_togru = nullptr, *p_gi = nullptr, *p_gh = nullptr;
    __nv_bfloat16 *p_Ahi = nullptr, *p_Alo = nullptr;
    cudaGetSymbolAddress((void**)&p_togru, g_togru);
    cudaGetSymbolAddress((void**)&p_gi,    g_gi);
    cudaGetSymbolAddress((void**)&p_gh,    g_gh);
    cudaGetSymbolAddress((void**)&p_Ahi,   g_Ahi);
    cudaGetSymbolAddress((void**)&p_Alo,   g_Alo);

    cudaFuncSetAttribute(k_logits, cudaFuncAttributeMaxDynamicSharedMemorySize, SMEM_LOGITS);

    k_u2<<<1, 1024>>>(attn_w, v);
    k_emb<<<BB, 256>>>(x, emb);
    k_scores<<<(BB * SS + 7) / 8, 256>>>(enc);
    k_softmax<<<BB, 256>>>();
    k_context<<<dim3(BB, H2 / 256), 256>>>(enc);
    k_sgemm<<<H3 / 128, 256>>>(p_togru, w_ih, b_ih, p_gi, H3, KG);
    k_sgemm<<<H3 / 128, 256>>>(hidden, w_hh, b_hh, p_gh, H3, HH);
    k_gates<<<BB * HH / 256, 256>>>(hidden, out_hidden);
    k_convA<<<(BB * KO / 4) / 256, 256>>>();
    k_logits<<<(VV + NTL - 1) / NTL, 256, SMEM_LOGITS>>>(p_Ahi, p_Alo, out_w, out_b, out_logits);
}